// round 9
// baseline (speedup 1.0000x reference)
#include <cuda_runtime.h>
#include <cuda_bf16.h>
#include <math.h>
#include <stdint.h>

#define BH    32
#define SEQ   2048
#define DIM   1024
#define NH    16
#define HDIM  64
#define MROWS 4096

// ---------------- device scratch ----------------
__device__ __nv_bfloat16 g_xh[MROWS * DIM], g_xl[MROWS * DIM];
__device__ __nv_bfloat16 g_Wqh[DIM * DIM], g_Wql[DIM * DIM];
__device__ __nv_bfloat16 g_Wkh[DIM * DIM], g_Wkl[DIM * DIM];
__device__ __nv_bfloat16 g_Wvh[DIM * DIM], g_Wvl[DIM * DIM];
__device__ __nv_bfloat16 g_Woh[DIM * DIM], g_Wol[DIM * DIM];
__device__ __nv_bfloat16 g_Qh[BH * SEQ * HDIM], g_Ql[BH * SEQ * HDIM];
__device__ __nv_bfloat16 g_Kh[BH * SEQ * HDIM], g_Kl[BH * SEQ * HDIM];
__device__ __nv_bfloat16 g_Vth[BH * HDIM * SEQ], g_Vtl[BH * HDIM * SEQ];
__device__ __nv_bfloat16 g_Ph[(size_t)BH * SEQ * SEQ], g_Pl[(size_t)BH * SEQ * SEQ];
__device__ float         g_rowsum[BH * SEQ];
__device__ __nv_bfloat16 g_Ah[(size_t)MROWS * DIM], g_Al[(size_t)MROWS * DIM];

// ---------------- helpers ----------------
__device__ __forceinline__ uint32_t smem_u32(const void* p) {
    uint32_t a;
    asm("{ .reg .u64 t; cvta.to.shared.u64 t, %1; cvt.u32.u64 %0, t; }" : "=r"(a) : "l"(p));
    return a;
}
__device__ __forceinline__ void cp16(uint32_t s, const void* g) {
    asm volatile("cp.async.cg.shared.global [%0], [%1], 16;" :: "r"(s), "l"(g));
}
__device__ __forceinline__ void mma_bf16(float* d, const uint32_t* a, const uint32_t* b) {
    asm volatile(
        "mma.sync.aligned.m16n8k16.row.col.f32.bf16.bf16.f32 "
        "{%0,%1,%2,%3}, {%4,%5,%6,%7}, {%8,%9}, {%0,%1,%2,%3};"
        : "+f"(d[0]), "+f"(d[1]), "+f"(d[2]), "+f"(d[3])
        : "r"(a[0]), "r"(a[1]), "r"(a[2]), "r"(a[3]), "r"(b[0]), "r"(b[1]));
}
__device__ __forceinline__ void split2(float v0, float v1, uint32_t& h, uint32_t& l) {
    __nv_bfloat16 h0 = __float2bfloat16(v0), h1 = __float2bfloat16(v1);
    h = ((uint32_t)__bfloat16_as_ushort(h1) << 16) | __bfloat16_as_ushort(h0);
    __nv_bfloat16 l0 = __float2bfloat16(v0 - __bfloat162float(h0));
    __nv_bfloat16 l1 = __float2bfloat16(v1 - __bfloat162float(h1));
    l = ((uint32_t)__bfloat16_as_ushort(l1) << 16) | __bfloat16_as_ushort(l0);
}

// ---------------- GEMM parameter block ----------------
struct GP {
    const __nv_bfloat16 *Ah, *Al, *Bh, *Bl;
    long strideA, bStrideA, strideB, bStrideB;
    const float* bias;
    float scale;
    int Ktot, mode;
    __nv_bfloat16 *outH, *outL;
    float *outF, *rowsum;
};

// ---------------- split conversion kernels ----------------
__global__ __launch_bounds__(256) void split_kernel(const float* __restrict__ in,
                                                    __nv_bfloat16* __restrict__ h,
                                                    __nv_bfloat16* __restrict__ l, int n) {
    int i = blockIdx.x * 256 + threadIdx.x;
    if (i < n) {
        float v = in[i];
        __nv_bfloat16 hi = __float2bfloat16(v);
        h[i] = hi;
        l[i] = __float2bfloat16(v - __bfloat162float(hi));
    }
}

struct WS { const float* W[4]; __nv_bfloat16 *th[4], *tl[4]; };
__global__ __launch_bounds__(256) void wsplit4_kernel(WS ws) {
    __shared__ float t[32][33];
    const float* W = ws.W[blockIdx.z];
    __nv_bfloat16* th = ws.th[blockIdx.z];
    __nv_bfloat16* tl = ws.tl[blockIdx.z];
    int n0 = blockIdx.x * 32, k0 = blockIdx.y * 32;
    int tx = threadIdx.x & 31, ty = threadIdx.x >> 5;
#pragma unroll
    for (int r = ty; r < 32; r += 8)
        t[r][tx] = W[(size_t)(k0 + r) * DIM + n0 + tx];
    __syncthreads();
#pragma unroll
    for (int r = ty; r < 32; r += 8) {
        float v = t[tx][r];
        __nv_bfloat16 hi = __float2bfloat16(v);
        size_t idx = (size_t)(n0 + r) * DIM + k0 + tx;
        th[idx] = hi;
        tl[idx] = __float2bfloat16(v - __bfloat162float(hi));
    }
}

// ---------------- mma.sync split-bf16 GEMM body (R3 config: 8 warps 4Mx2N) --------
// modes: 0 Q/K head-split hi/lo, 1 V transposed hi/lo, 2 fp32 out (+bias),
//        3 exp(scores) -> P hi/lo + atomic row sums, 4 merged-head / rowsum
template <int TN>
__device__ __forceinline__ void gemm_body(const GP& P, int bx, int by, int bz) {
    extern __shared__ char smem[];
    constexpr int WN  = TN / 2;
    constexpr int NT  = WN / 8;
    constexpr int ROWB = 80;
    constexpr int A_H = 0;
    constexpr int A_L = 128 * ROWB;
    constexpr int B_H = 2 * 128 * ROWB;
    constexpr int B_L = 2 * 128 * ROWB + TN * ROWB;
    constexpr int STAGE = 2 * 128 * ROWB + 2 * TN * ROWB;

    const int tid = threadIdx.x;
    const int w = tid >> 5, lane = tid & 31;
    const int g = lane >> 2, t = lane & 3;
    const int wm = w & 3, wn = w >> 2;
    const __nv_bfloat16* Ah = P.Ah + (size_t)bz * P.bStrideA;
    const __nv_bfloat16* Al = P.Al + (size_t)bz * P.bStrideA;
    const __nv_bfloat16* Bh = P.Bh + (size_t)bz * P.bStrideB;
    const __nv_bfloat16* Bl = P.Bl + (size_t)bz * P.bStrideB;
    const long strideA = P.strideA, strideB = P.strideB;

    const int m0 = by * 128, n0 = bx * TN;
    const int nch = P.Ktot >> 5;
    const uint32_t sb = smem_u32(smem);

    float acc[2][NT][4];
#pragma unroll
    for (int i = 0; i < 2; i++)
#pragma unroll
        for (int j = 0; j < NT; j++)
#pragma unroll
            for (int k = 0; k < 4; k++) acc[i][j][k] = 0.f;

    auto stage_load = [&](int buf, int c) {
        const int k0 = c << 5;
        const uint32_t so = sb + buf * STAGE;
#pragma unroll
        for (int i = tid; i < 512; i += 256) {
            int r = i >> 2, cc = i & 3;
            uint32_t off = r * ROWB + cc * 16;
            cp16(so + A_H + off, Ah + (size_t)(m0 + r) * strideA + k0 + cc * 8);
            cp16(so + A_L + off, Al + (size_t)(m0 + r) * strideA + k0 + cc * 8);
        }
#pragma unroll
        for (int i = tid; i < TN * 4; i += 256) {
            int r = i >> 2, cc = i & 3;
            uint32_t off = r * ROWB + cc * 16;
            cp16(so + B_H + off, Bh + (size_t)(n0 + r) * strideB + k0 + cc * 8);
            cp16(so + B_L + off, Bl + (size_t)(n0 + r) * strideB + k0 + cc * 8);
        }
        asm volatile("cp.async.commit_group;");
    };

    stage_load(0, 0);
    for (int c = 0; c < nch; c++) {
        const int buf = c & 1;
        if (c + 1 < nch) {
            stage_load(buf ^ 1, c + 1);
            asm volatile("cp.async.wait_group 1;");
        } else {
            asm volatile("cp.async.wait_group 0;");
        }
        __syncthreads();

        const char* s = smem + buf * STAGE;
#pragma unroll
        for (int ks = 0; ks < 2; ks++) {
            const int kb = ks * 32 + t * 4;
            uint32_t ah[2][4], al[2][4], bh[NT][2], bl[NT][2];
#pragma unroll
            for (int mt = 0; mt < 2; mt++) {
                const char* p = s + (wm * 32 + mt * 16 + g) * ROWB + kb;
                ah[mt][0] = *(const uint32_t*)(p + A_H);
                ah[mt][1] = *(const uint32_t*)(p + A_H + 8 * ROWB);
                ah[mt][2] = *(const uint32_t*)(p + A_H + 16);
                ah[mt][3] = *(const uint32_t*)(p + A_H + 8 * ROWB + 16);
                al[mt][0] = *(const uint32_t*)(p + A_L);
                al[mt][1] = *(const uint32_t*)(p + A_L + 8 * ROWB);
                al[mt][2] = *(const uint32_t*)(p + A_L + 16);
                al[mt][3] = *(const uint32_t*)(p + A_L + 8 * ROWB + 16);
            }
#pragma unroll
            for (int nt = 0; nt < NT; nt++) {
                const char* p = s + (wn * WN + nt * 8 + g) * ROWB + kb;
                bh[nt][0] = *(const uint32_t*)(p + B_H);
                bh[nt][1] = *(const uint32_t*)(p + B_H + 16);
                bl[nt][0] = *(const uint32_t*)(p + B_L);
                bl[nt][1] = *(const uint32_t*)(p + B_L + 16);
            }
#pragma unroll
            for (int mt = 0; mt < 2; mt++)
#pragma unroll
                for (int nt = 0; nt < NT; nt++) {
                    mma_bf16(acc[mt][nt], ah[mt], bh[nt]);
                    mma_bf16(acc[mt][nt], ah[mt], bl[nt]);
                    mma_bf16(acc[mt][nt], al[mt], bh[nt]);
                }
        }
        __syncthreads();
    }

    // ---------------- epilogue ----------------
    const int mode = P.mode;
    if (mode == 3) {
        float rs[2][2] = {};
#pragma unroll
        for (int mt = 0; mt < 2; mt++)
#pragma unroll
            for (int nt = 0; nt < NT; nt++)
#pragma unroll
                for (int p = 0; p < 2; p++) {
                    float e0 = __expf(acc[mt][nt][2 * p + 0]);
                    float e1 = __expf(acc[mt][nt][2 * p + 1]);
                    acc[mt][nt][2 * p + 0] = e0;
                    acc[mt][nt][2 * p + 1] = e1;
                    rs[mt][p] += e0 + e1;
                }
#pragma unroll
        for (int mt = 0; mt < 2; mt++)
#pragma unroll
            for (int p = 0; p < 2; p++) {
                int row = m0 + wm * 32 + mt * 16 + g + 8 * p;
#pragma unroll
                for (int nt = 0; nt < NT; nt++) {
                    int col = n0 + wn * WN + nt * 8 + 2 * t;
                    size_t ofs = (size_t)bz * SEQ * SEQ + (size_t)row * SEQ + col;
                    uint32_t hh, ll;
                    split2(acc[mt][nt][2 * p + 0], acc[mt][nt][2 * p + 1], hh, ll);
                    *(uint32_t*)(P.outH + ofs) = hh;
                    *(uint32_t*)(P.outL + ofs) = ll;
                }
                float s2 = rs[mt][p];
                s2 += __shfl_xor_sync(0xffffffffu, s2, 1);
                s2 += __shfl_xor_sync(0xffffffffu, s2, 2);
                if (t == 0) atomicAdd(&P.rowsum[bz * SEQ + row], s2);
            }
        return;
    }

#pragma unroll
    for (int mt = 0; mt < 2; mt++)
#pragma unroll
        for (int nt = 0; nt < NT; nt++)
#pragma unroll
            for (int p = 0; p < 2; p++) {
                int row = m0 + wm * 32 + mt * 16 + g + 8 * p;
                int col = n0 + wn * WN + nt * 8 + 2 * t;
                float v0 = acc[mt][nt][2 * p + 0];
                float v1 = acc[mt][nt][2 * p + 1];
                if (mode == 0 || mode == 1) {
                    int b = row >> 11, sq = row & (SEQ - 1);
                    v0 = (v0 + P.bias[col]) * P.scale;
                    v1 = (v1 + P.bias[col + 1]) * P.scale;
#pragma unroll
                    for (int e = 0; e < 2; e++) {
                        int cc = col + e;
                        float v = e ? v1 : v0;
                        int h = cc >> 6, hd = cc & (HDIM - 1);
                        __nv_bfloat16 hi = __float2bfloat16(v);
                        __nv_bfloat16 lo = __float2bfloat16(v - __bfloat162float(hi));
                        size_t idx = (mode == 0)
                            ? ((((size_t)b * NH + h) * SEQ + sq) * HDIM + hd)
                            : ((((size_t)b * NH + h) * HDIM + hd) * SEQ + sq);
                        P.outH[idx] = hi;
                        P.outL[idx] = lo;
                    }
                } else if (mode == 2) {
                    *(float2*)(P.outF + (size_t)row * DIM + col)
                        = make_float2(v0 + P.bias[col], v1 + P.bias[col + 1]);
                } else {  // mode 4
                    float inv = 1.0f / P.rowsum[bz * SEQ + row];
                    v0 *= inv;
                    v1 *= inv;
                    int b = bz >> 4, h = bz & (NH - 1);
                    size_t base = ((size_t)b * SEQ + row) * DIM + h * HDIM + col;
                    uint32_t hh, ll;
                    split2(v0, v1, hh, ll);
                    *(uint32_t*)(P.outH + base) = hh;
                    *(uint32_t*)(P.outL + base) = ll;
                }
            }
}

// ---------------- kernel wrappers ----------------
template <int TN>
__global__ __launch_bounds__(256, 1) void gemm_single(GP p) {
    gemm_body<TN>(p, blockIdx.x, blockIdx.y, blockIdx.z);
}
// Q-proj (256 blocks) + K-proj (256 blocks), both grid (8, 32)
__global__ __launch_bounds__(256, 1) void gemm_qk(GP q, GP k) {
    int bid = blockIdx.x;
    if (bid < 256) gemm_body<128>(q, bid & 7, bid >> 3, 0);
    else { bid -= 256; gemm_body<128>(k, bid & 7, bid >> 3, 0); }
}
// V-proj (256 long blocks FIRST) + scores (8192 short blocks, grid (16,16,32))
__global__ __launch_bounds__(256, 1) void gemm_vs(GP v, GP s) {
    int bid = blockIdx.x;
    if (bid < 256) gemm_body<128>(v, bid & 7, bid >> 3, 0);
    else {
        int sid = bid - 256;
        gemm_body<128>(s, sid & 15, (sid >> 4) & 15, sid >> 8);
    }
}

// ---------------- host ----------------
static void* sym(const void* s) { void* p; cudaGetSymbolAddress(&p, s); return p; }

extern "C" void kernel_launch(void* const* d_in, const int* in_sizes, int n_in,
                              void* d_out, int out_size)
{
    const float* x  = (const float*)d_in[0];
    const float* Wq = (const float*)d_in[1];
    const float* bq = (const float*)d_in[2];
    const float* Wk = (const float*)d_in[3];
    const float* bk = (const float*)d_in[4];
    const float* Wv = (const float*)d_in[5];
    const float* bv = (const float*)d_in[6];
    const float* Wo = (const float*)d_in[7];
    const float* bo = (const float*)d_in[8];
    float* out = (float*)d_out;

    constexpr int SMEM128 = 2 * (2 * 128 * 80 + 2 * 128 * 80);  // 81920
    constexpr int SMEM64  = 2 * (2 * 128 * 80 + 2 * 64 * 80);   // 61440
    cudaFuncSetAttribute(gemm_single<128>, cudaFuncAttributeMaxDynamicSharedMemorySize, SMEM128);
    cudaFuncSetAttribute(gemm_single<64>,  cudaFuncAttributeMaxDynamicSharedMemorySize, SMEM64);
    cudaFuncSetAttribute(gemm_qk, cudaFuncAttributeMaxDynamicSharedMemorySize, SMEM128);
    cudaFuncSetAttribute(gemm_vs, cudaFuncAttributeMaxDynamicSharedMemorySize, SMEM128);

    __nv_bfloat16 *xh = (__nv_bfloat16*)sym(g_xh), *xl = (__nv_bfloat16*)sym(g_xl);
    __nv_bfloat16 *wqh = (__nv_bfloat16*)sym(g_Wqh), *wql = (__nv_bfloat16*)sym(g_Wql);
    __nv_bfloat16 *wkh = (__nv_bfloat16*)sym(g_Wkh), *wkl = (__nv_bfloat16*)sym(g_Wkl);
    __nv_bfloat16 *wvh = (__nv_bfloat16*)sym(g_Wvh), *wvl = (__nv_bfloat16*)sym(g_Wvl);
    __nv_bfloat16 *woh = (__nv_bfloat16*)sym(g_Woh), *wol = (__nv_bfloat16*)sym(g_Wol);
    __nv_bfloat16 *qh = (__nv_bfloat16*)sym(g_Qh), *ql = (__nv_bfloat16*)sym(g_Ql);
    __nv_bfloat16 *kh = (__nv_bfloat16*)sym(g_Kh), *kl = (__nv_bfloat16*)sym(g_Kl);
    __nv_bfloat16 *vth = (__nv_bfloat16*)sym(g_Vth), *vtl = (__nv_bfloat16*)sym(g_Vtl);
    __nv_bfloat16 *pwh = (__nv_bfloat16*)sym(g_Ph), *pwl = (__nv_bfloat16*)sym(g_Pl);
    __nv_bfloat16 *ah = (__nv_bfloat16*)sym(g_Ah), *al = (__nv_bfloat16*)sym(g_Al);
    float* rsum = (float*)sym(g_rowsum);

    cudaMemsetAsync(rsum, 0, BH * SEQ * sizeof(float), 0);

    split_kernel<<<(MROWS * DIM + 255) / 256, 256>>>(x, xh, xl, MROWS * DIM);

    WS ws;
    ws.W[0] = Wq;  ws.th[0] = wqh;  ws.tl[0] = wql;
    ws.W[1] = Wk;  ws.th[1] = wkh;  ws.tl[1] = wkl;
    ws.W[2] = Wv;  ws.th[2] = wvh;  ws.tl[2] = wvl;
    ws.W[3] = Wo;  ws.th[3] = woh;  ws.tl[3] = wol;
    wsplit4_kernel<<<dim3(DIM / 32, DIM / 32, 4), 256>>>(ws);

    dim3 blk(256);

    GP q = {xh, xl, wqh, wql, DIM, 0, DIM, 0, bq, 0.125f, DIM, 0, qh, ql, nullptr, nullptr};
    GP k = {xh, xl, wkh, wkl, DIM, 0, DIM, 0, bk, 1.0f,   DIM, 0, kh, kl, nullptr, nullptr};
    GP v = {xh, xl, wvh, wvl, DIM, 0, DIM, 0, bv, 1.0f,   DIM, 1, vth, vtl, nullptr, nullptr};
    GP s = {qh, ql, kh, kl, HDIM, (long)SEQ * HDIM, HDIM, (long)SEQ * HDIM,
            nullptr, 1.0f, HDIM, 3, pwh, pwl, nullptr, rsum};
    GP av = {pwh, pwl, vth, vtl, SEQ, (long)SEQ * SEQ, SEQ, (long)HDIM * SEQ,
             nullptr, 1.0f, SEQ, 4, ah, al, nullptr, rsum};
    GP o = {ah, al, woh, wol, DIM, 0, DIM, 0, bo, 1.0f, DIM, 2,
            nullptr, nullptr, out, nullptr};

    gemm_qk<<<512, blk, SMEM128>>>(q, k);
    gemm_vs<<<256 + 8192, blk, SMEM128>>>(v, s);
    gemm_single<64><<<dim3(1, SEQ / 128, BH), blk, SMEM64>>>(av);
    gemm_single<128><<<dim3(DIM / 128, MROWS / 128, 1), blk, SMEM128>>>(o);
}

// round 11
// speedup vs baseline: 1.0772x; 1.0772x over previous
#include <cuda_runtime.h>
#include <cuda_bf16.h>
#include <math.h>
#include <stdint.h>

#define BH    32
#define SEQ   2048
#define DIM   1024
#define NH    16
#define HDIM  64
#define MROWS 4096

// ---------------- device scratch ----------------
__device__ __nv_bfloat16 g_xh[MROWS * DIM], g_xl[MROWS * DIM];
__device__ __nv_bfloat16 g_Wqh[DIM * DIM], g_Wql[DIM * DIM];
__device__ __nv_bfloat16 g_Wkh[DIM * DIM], g_Wkl[DIM * DIM];
__device__ __nv_bfloat16 g_Wvh[DIM * DIM], g_Wvl[DIM * DIM];
__device__ __nv_bfloat16 g_Woh[DIM * DIM], g_Wol[DIM * DIM];
__device__ __nv_bfloat16 g_Qh[BH * SEQ * HDIM], g_Ql[BH * SEQ * HDIM];
__device__ __nv_bfloat16 g_Kh[BH * SEQ * HDIM], g_Kl[BH * SEQ * HDIM];
__device__ __nv_bfloat16 g_Vth[BH * HDIM * SEQ], g_Vtl[BH * HDIM * SEQ];
__device__ __nv_bfloat16 g_Ph[(size_t)BH * SEQ * SEQ], g_Pl[(size_t)BH * SEQ * SEQ];
__device__ float         g_rowsum[BH * SEQ];
__device__ __nv_bfloat16 g_Ah[(size_t)MROWS * DIM], g_Al[(size_t)MROWS * DIM];

// ---------------- helpers ----------------
__device__ __forceinline__ uint32_t smem_u32(const void* p) {
    uint32_t a;
    asm("{ .reg .u64 t; cvta.to.shared.u64 t, %1; cvt.u32.u64 %0, t; }" : "=r"(a) : "l"(p));
    return a;
}
__device__ __forceinline__ void cp16(uint32_t s, const void* g) {
    asm volatile("cp.async.cg.shared.global [%0], [%1], 16;" :: "r"(s), "l"(g));
}
__device__ __forceinline__ void mma_bf16(float* d, const uint32_t* a, const uint32_t* b) {
    asm volatile(
        "mma.sync.aligned.m16n8k16.row.col.f32.bf16.bf16.f32 "
        "{%0,%1,%2,%3}, {%4,%5,%6,%7}, {%8,%9}, {%0,%1,%2,%3};"
        : "+f"(d[0]), "+f"(d[1]), "+f"(d[2]), "+f"(d[3])
        : "r"(a[0]), "r"(a[1]), "r"(a[2]), "r"(a[3]), "r"(b[0]), "r"(b[1]));
}
__device__ __forceinline__ void split2(float v0, float v1, uint32_t& h, uint32_t& l) {
    __nv_bfloat16 h0 = __float2bfloat16(v0), h1 = __float2bfloat16(v1);
    h = ((uint32_t)__bfloat16_as_ushort(h1) << 16) | __bfloat16_as_ushort(h0);
    __nv_bfloat16 l0 = __float2bfloat16(v0 - __bfloat162float(h0));
    __nv_bfloat16 l1 = __float2bfloat16(v1 - __bfloat162float(h1));
    l = ((uint32_t)__bfloat16_as_ushort(l1) << 16) | __bfloat16_as_ushort(l0);
}

// ---------------- GEMM parameter block ----------------
struct GP {
    const __nv_bfloat16 *Ah, *Al, *Bh, *Bl;
    long strideA, bStrideA, strideB, bStrideB;
    const float* bias;
    float scale;
    int Ktot, mode;
    __nv_bfloat16 *outH, *outL;
    float *outF, *rowsum;
};

// ---------------- split conversion kernels ----------------
__global__ __launch_bounds__(256) void split_kernel(const float* __restrict__ in,
                                                    __nv_bfloat16* __restrict__ h,
                                                    __nv_bfloat16* __restrict__ l, int n) {
    int i = blockIdx.x * 256 + threadIdx.x;
    if (i < n) {
        float v = in[i];
        __nv_bfloat16 hi = __float2bfloat16(v);
        h[i] = hi;
        l[i] = __float2bfloat16(v - __bfloat162float(hi));
    }
}

struct WS { const float* W[4]; __nv_bfloat16 *th[4], *tl[4]; };
__global__ __launch_bounds__(256) void wsplit4_kernel(WS ws) {
    __shared__ float t[32][33];
    const float* W = ws.W[blockIdx.z];
    __nv_bfloat16* th = ws.th[blockIdx.z];
    __nv_bfloat16* tl = ws.tl[blockIdx.z];
    int n0 = blockIdx.x * 32, k0 = blockIdx.y * 32;
    int tx = threadIdx.x & 31, ty = threadIdx.x >> 5;
#pragma unroll
    for (int r = ty; r < 32; r += 8)
        t[r][tx] = W[(size_t)(k0 + r) * DIM + n0 + tx];
    __syncthreads();
#pragma unroll
    for (int r = ty; r < 32; r += 8) {
        float v = t[tx][r];
        __nv_bfloat16 hi = __float2bfloat16(v);
        size_t idx = (size_t)(n0 + r) * DIM + k0 + tx;
        th[idx] = hi;
        tl[idx] = __float2bfloat16(v - __bfloat162float(hi));
    }
}

// ---------------- mma.sync split-bf16 GEMM: CTA 128x64, 8 warps (4M x 2N, 32x32) --
// 2 CTAs/SM target. modes: 0 Q/K head-split hi/lo, 1 V transposed hi/lo,
// 2 fp32 out (+bias), 3 exp(scores) -> P hi/lo + atomic rowsum, 4 merged / rowsum
__global__ __launch_bounds__(256, 2) void gemm_kernel(GP P)
{
    extern __shared__ char smem[];
    constexpr int TN = 64, WN = 32, NT = 4;
    constexpr int ROWB = 80;
    constexpr int A_H = 0;
    constexpr int A_L = 128 * ROWB;
    constexpr int B_H = 2 * 128 * ROWB;
    constexpr int B_L = 2 * 128 * ROWB + TN * ROWB;
    constexpr int STAGE = 2 * 128 * ROWB + 2 * TN * ROWB;   // 30720

    const int tid = threadIdx.x;
    const int w = tid >> 5, lane = tid & 31;
    const int g = lane >> 2, t = lane & 3;
    const int wm = w & 3, wn = w >> 2;
    const int bx = blockIdx.x, by = blockIdx.y, bz = blockIdx.z;
    const __nv_bfloat16* Ah = P.Ah + (size_t)bz * P.bStrideA;
    const __nv_bfloat16* Al = P.Al + (size_t)bz * P.bStrideA;
    const __nv_bfloat16* Bh = P.Bh + (size_t)bz * P.bStrideB;
    const __nv_bfloat16* Bl = P.Bl + (size_t)bz * P.bStrideB;
    const long strideA = P.strideA, strideB = P.strideB;

    const int m0 = by * 128, n0 = bx * TN;
    const int nch = P.Ktot >> 5;
    const uint32_t sb = smem_u32(smem);

    float acc[2][NT][4];
#pragma unroll
    for (int i = 0; i < 2; i++)
#pragma unroll
        for (int j = 0; j < NT; j++)
#pragma unroll
            for (int k = 0; k < 4; k++) acc[i][j][k] = 0.f;

    auto stage_load = [&](int buf, int c) {
        const int k0 = c << 5;
        const uint32_t so = sb + buf * STAGE;
#pragma unroll
        for (int i = tid; i < 512; i += 256) {
            int r = i >> 2, cc = i & 3;
            uint32_t off = r * ROWB + cc * 16;
            cp16(so + A_H + off, Ah + (size_t)(m0 + r) * strideA + k0 + cc * 8);
            cp16(so + A_L + off, Al + (size_t)(m0 + r) * strideA + k0 + cc * 8);
        }
        {
            int r = tid >> 2, cc = tid & 3;          // 256 = TN*4 exactly
            uint32_t off = r * ROWB + cc * 16;
            cp16(so + B_H + off, Bh + (size_t)(n0 + r) * strideB + k0 + cc * 8);
            cp16(so + B_L + off, Bl + (size_t)(n0 + r) * strideB + k0 + cc * 8);
        }
        asm volatile("cp.async.commit_group;");
    };

    stage_load(0, 0);
    for (int c = 0; c < nch; c++) {
        const int buf = c & 1;
        if (c + 1 < nch) {
            stage_load(buf ^ 1, c + 1);
            asm volatile("cp.async.wait_group 1;");
        } else {
            asm volatile("cp.async.wait_group 0;");
        }
        __syncthreads();

        const char* s = smem + buf * STAGE;
#pragma unroll
        for (int ks = 0; ks < 2; ks++) {
            const int kb = ks * 32 + t * 4;
            uint32_t ah[2][4], al[2][4], bh[NT][2], bl[NT][2];
#pragma unroll
            for (int mt = 0; mt < 2; mt++) {
                const char* p = s + (wm * 32 + mt * 16 + g) * ROWB + kb;
                ah[mt][0] = *(const uint32_t*)(p + A_H);
                ah[mt][1] = *(const uint32_t*)(p + A_H + 8 * ROWB);
                ah[mt][2] = *(const uint32_t*)(p + A_H + 16);
                ah[mt][3] = *(const uint32_t*)(p + A_H + 8 * ROWB + 16);
                al[mt][0] = *(const uint32_t*)(p + A_L);
                al[mt][1] = *(const uint32_t*)(p + A_L + 8 * ROWB);
                al[mt][2] = *(const uint32_t*)(p + A_L + 16);
                al[mt][3] = *(const uint32_t*)(p + A_L + 8 * ROWB + 16);
            }
#pragma unroll
            for (int nt = 0; nt < NT; nt++) {
                const char* p = s + (wn * WN + nt * 8 + g) * ROWB + kb;
                bh[nt][0] = *(const uint32_t*)(p + B_H);
                bh[nt][1] = *(const uint32_t*)(p + B_H + 16);
                bl[nt][0] = *(const uint32_t*)(p + B_L);
                bl[nt][1] = *(const uint32_t*)(p + B_L + 16);
            }
#pragma unroll
            for (int mt = 0; mt < 2; mt++)
#pragma unroll
                for (int nt = 0; nt < NT; nt++) {
                    mma_bf16(acc[mt][nt], ah[mt], bh[nt]);
                    mma_bf16(acc[mt][nt], ah[mt], bl[nt]);
                    mma_bf16(acc[mt][nt], al[mt], bh[nt]);
                }
        }
        __syncthreads();
    }

    // ---------------- epilogue ----------------
    const int mode = P.mode;
    if (mode == 3) {
        float rs[2][2] = {};
#pragma unroll
        for (int mt = 0; mt < 2; mt++)
#pragma unroll
            for (int nt = 0; nt < NT; nt++)
#pragma unroll
                for (int p = 0; p < 2; p++) {
                    float e0 = __expf(acc[mt][nt][2 * p + 0]);
                    float e1 = __expf(acc[mt][nt][2 * p + 1]);
                    acc[mt][nt][2 * p + 0] = e0;
                    acc[mt][nt][2 * p + 1] = e1;
                    rs[mt][p] += e0 + e1;
                }
#pragma unroll
        for (int mt = 0; mt < 2; mt++)
#pragma unroll
            for (int p = 0; p < 2; p++) {
                int row = m0 + wm * 32 + mt * 16 + g + 8 * p;
#pragma unroll
                for (int nt = 0; nt < NT; nt++) {
                    int col = n0 + wn * WN + nt * 8 + 2 * t;
                    size_t ofs = (size_t)bz * SEQ * SEQ + (size_t)row * SEQ + col;
                    uint32_t hh, ll;
                    split2(acc[mt][nt][2 * p + 0], acc[mt][nt][2 * p + 1], hh, ll);
                    *(uint32_t*)(P.outH + ofs) = hh;
                    *(uint32_t*)(P.outL + ofs) = ll;
                }
                float s2 = rs[mt][p];
                s2 += __shfl_xor_sync(0xffffffffu, s2, 1);
                s2 += __shfl_xor_sync(0xffffffffu, s2, 2);
                if (t == 0) atomicAdd(&P.rowsum[bz * SEQ + row], s2);
            }
        return;
    }

#pragma unroll
    for (int mt = 0; mt < 2; mt++)
#pragma unroll
        for (int nt = 0; nt < NT; nt++)
#pragma unroll
            for (int p = 0; p < 2; p++) {
                int row = m0 + wm * 32 + mt * 16 + g + 8 * p;
                int col = n0 + wn * WN + nt * 8 + 2 * t;
                float v0 = acc[mt][nt][2 * p + 0];
                float v1 = acc[mt][nt][2 * p + 1];
                if (mode == 0 || mode == 1) {
                    int b = row >> 11, sq = row & (SEQ - 1);
                    v0 = (v0 + P.bias[col]) * P.scale;
                    v1 = (v1 + P.bias[col + 1]) * P.scale;
#pragma unroll
                    for (int e = 0; e < 2; e++) {
                        int cc = col + e;
                        float v = e ? v1 : v0;
                        int h = cc >> 6, hd = cc & (HDIM - 1);
                        __nv_bfloat16 hi = __float2bfloat16(v);
                        __nv_bfloat16 lo = __float2bfloat16(v - __bfloat162float(hi));
                        size_t idx = (mode == 0)
                            ? ((((size_t)b * NH + h) * SEQ + sq) * HDIM + hd)
                            : ((((size_t)b * NH + h) * HDIM + hd) * SEQ + sq);
                        P.outH[idx] = hi;
                        P.outL[idx] = lo;
                    }
                } else if (mode == 2) {
                    *(float2*)(P.outF + (size_t)row * DIM + col)
                        = make_float2(v0 + P.bias[col], v1 + P.bias[col + 1]);
                } else {  // mode 4
                    float inv = 1.0f / P.rowsum[bz * SEQ + row];
                    v0 *= inv;
                    v1 *= inv;
                    int b = bz >> 4, h = bz & (NH - 1);
                    size_t base = ((size_t)b * SEQ + row) * DIM + h * HDIM + col;
                    uint32_t hh, ll;
                    split2(v0, v1, hh, ll);
                    *(uint32_t*)(P.outH + base) = hh;
                    *(uint32_t*)(P.outL + base) = ll;
                }
            }
}

// ---------------- host ----------------
static void* sym(const void* s) { void* p; cudaGetSymbolAddress(&p, s); return p; }

extern "C" void kernel_launch(void* const* d_in, const int* in_sizes, int n_in,
                              void* d_out, int out_size)
{
    const float* x  = (const float*)d_in[0];
    const float* Wq = (const float*)d_in[1];
    const float* bq = (const float*)d_in[2];
    const float* Wk = (const float*)d_in[3];
    const float* bk = (const float*)d_in[4];
    const float* Wv = (const float*)d_in[5];
    const float* bv = (const float*)d_in[6];
    const float* Wo = (const float*)d_in[7];
    const float* bo = (const float*)d_in[8];
    float* out = (float*)d_out;

    constexpr int SMEM = 2 * (2 * 128 * 80 + 2 * 64 * 80);   // 61440
    cudaFuncSetAttribute(gemm_kernel, cudaFuncAttributeMaxDynamicSharedMemorySize, SMEM);

    __nv_bfloat16 *xh = (__nv_bfloat16*)sym(g_xh), *xl = (__nv_bfloat16*)sym(g_xl);
    __nv_bfloat16 *wqh = (__nv_bfloat16*)sym(g_Wqh), *wql = (__nv_bfloat16*)sym(g_Wql);
    __nv_bfloat16 *wkh = (__nv_bfloat16*)sym(g_Wkh), *wkl = (__nv_bfloat16*)sym(g_Wkl);
    __nv_bfloat16 *wvh = (__nv_bfloat16*)sym(g_Wvh), *wvl = (__nv_bfloat16*)sym(g_Wvl);
    __nv_bfloat16 *woh = (__nv_bfloat16*)sym(g_Woh), *wol = (__nv_bfloat16*)sym(g_Wol);
    __nv_bfloat16 *qh = (__nv_bfloat16*)sym(g_Qh), *ql = (__nv_bfloat16*)sym(g_Ql);
    __nv_bfloat16 *kh = (__nv_bfloat16*)sym(g_Kh), *kl = (__nv_bfloat16*)sym(g_Kl);
    __nv_bfloat16 *vth = (__nv_bfloat16*)sym(g_Vth), *vtl = (__nv_bfloat16*)sym(g_Vtl);
    __nv_bfloat16 *pwh = (__nv_bfloat16*)sym(g_Ph), *pwl = (__nv_bfloat16*)sym(g_Pl);
    __nv_bfloat16 *ah = (__nv_bfloat16*)sym(g_Ah), *al = (__nv_bfloat16*)sym(g_Al);
    float* rsum = (float*)sym(g_rowsum);

    cudaMemsetAsync(rsum, 0, BH * SEQ * sizeof(float), 0);

    split_kernel<<<(MROWS * DIM + 255) / 256, 256>>>(x, xh, xl, MROWS * DIM);

    WS ws;
    ws.W[0] = Wq;  ws.th[0] = wqh;  ws.tl[0] = wql;
    ws.W[1] = Wk;  ws.th[1] = wkh;  ws.tl[1] = wkl;
    ws.W[2] = Wv;  ws.th[2] = wvh;  ws.tl[2] = wvl;
    ws.W[3] = Wo;  ws.th[3] = woh;  ws.tl[3] = wol;
    wsplit4_kernel<<<dim3(DIM / 32, DIM / 32, 4), 256>>>(ws);

    dim3 blk(256);
    dim3 gproj(DIM / 64, MROWS / 128, 1);   // 16 x 32 = 512 blocks

    GP q = {xh, xl, wqh, wql, DIM, 0, DIM, 0, bq, 0.125f, DIM, 0, qh, ql, nullptr, nullptr};
    GP k = {xh, xl, wkh, wkl, DIM, 0, DIM, 0, bk, 1.0f,   DIM, 0, kh, kl, nullptr, nullptr};
    GP v = {xh, xl, wvh, wvl, DIM, 0, DIM, 0, bv, 1.0f,   DIM, 1, vth, vtl, nullptr, nullptr};
    GP s = {qh, ql, kh, kl, HDIM, (long)SEQ * HDIM, HDIM, (long)SEQ * HDIM,
            nullptr, 1.0f, HDIM, 3, pwh, pwl, nullptr, rsum};
    GP av = {pwh, pwl, vth, vtl, SEQ, (long)SEQ * SEQ, SEQ, (long)HDIM * SEQ,
             nullptr, 1.0f, SEQ, 4, ah, al, nullptr, rsum};
    GP o = {ah, al, woh, wol, DIM, 0, DIM, 0, bo, 1.0f, DIM, 2,
            nullptr, nullptr, out, nullptr};

    gemm_kernel<<<gproj, blk, SMEM>>>(q);
    gemm_kernel<<<gproj, blk, SMEM>>>(k);
    gemm_kernel<<<gproj, blk, SMEM>>>(v);
    gemm_kernel<<<dim3(SEQ / 64, SEQ / 128, BH), blk, SMEM>>>(s);
    gemm_kernel<<<dim3(1, SEQ / 128, BH), blk, SMEM>>>(av);
    gemm_kernel<<<gproj, blk, SMEM>>>(o);
}

// round 12
// speedup vs baseline: 1.1209x; 1.0406x over previous
#include <cuda_runtime.h>
#include <cuda_bf16.h>
#include <math.h>
#include <stdint.h>

#define BH    32
#define SEQ   2048
#define DIM   1024
#define NH    16
#define HDIM  64
#define MROWS 4096

// ---------------- device scratch ----------------
__device__ __nv_bfloat16 g_xh[MROWS * DIM], g_xl[MROWS * DIM];
__device__ __nv_bfloat16 g_Wqh[DIM * DIM], g_Wql[DIM * DIM];
__device__ __nv_bfloat16 g_Wkh[DIM * DIM], g_Wkl[DIM * DIM];
__device__ __nv_bfloat16 g_Wvh[DIM * DIM], g_Wvl[DIM * DIM];
__device__ __nv_bfloat16 g_Woh[DIM * DIM], g_Wol[DIM * DIM];
__device__ __nv_bfloat16 g_Qh[BH * SEQ * HDIM], g_Ql[BH * SEQ * HDIM];
__device__ __nv_bfloat16 g_Kh[BH * SEQ * HDIM], g_Kl[BH * SEQ * HDIM];
__device__ __nv_bfloat16 g_Vth[BH * HDIM * SEQ], g_Vtl[BH * HDIM * SEQ];
__device__ __nv_bfloat16 g_Ph[(size_t)BH * SEQ * SEQ], g_Pl[(size_t)BH * SEQ * SEQ];
__device__ float         g_rowsum[BH * SEQ];
__device__ __nv_bfloat16 g_Ah[(size_t)MROWS * DIM], g_Al[(size_t)MROWS * DIM];

// ---------------- helpers ----------------
__device__ __forceinline__ uint32_t smem_u32(const void* p) {
    uint32_t a;
    asm("{ .reg .u64 t; cvta.to.shared.u64 t, %1; cvt.u32.u64 %0, t; }" : "=r"(a) : "l"(p));
    return a;
}
__device__ __forceinline__ void cp16(uint32_t s, const void* g) {
    asm volatile("cp.async.cg.shared.global [%0], [%1], 16;" :: "r"(s), "l"(g));
}
__device__ __forceinline__ void mma_bf16(float* d, const uint32_t* a, const uint32_t* b) {
    asm volatile(
        "mma.sync.aligned.m16n8k16.row.col.f32.bf16.bf16.f32 "
        "{%0,%1,%2,%3}, {%4,%5,%6,%7}, {%8,%9}, {%0,%1,%2,%3};"
        : "+f"(d[0]), "+f"(d[1]), "+f"(d[2]), "+f"(d[3])
        : "r"(a[0]), "r"(a[1]), "r"(a[2]), "r"(a[3]), "r"(b[0]), "r"(b[1]));
}
__device__ __forceinline__ void split2(float v0, float v1, uint32_t& h, uint32_t& l) {
    __nv_bfloat16 h0 = __float2bfloat16(v0), h1 = __float2bfloat16(v1);
    h = ((uint32_t)__bfloat16_as_ushort(h1) << 16) | __bfloat16_as_ushort(h0);
    __nv_bfloat16 l0 = __float2bfloat16(v0 - __bfloat162float(h0));
    __nv_bfloat16 l1 = __float2bfloat16(v1 - __bfloat162float(h1));
    l = ((uint32_t)__bfloat16_as_ushort(l1) << 16) | __bfloat16_as_ushort(l0);
}

// ---------------- GEMM parameter block ----------------
struct GP {
    const __nv_bfloat16 *Ah, *Al, *Bh, *Bl;
    long strideA, bStrideA, strideB, bStrideB;
    const float* bias;
    float scale;
    int Ktot, mode;
    __nv_bfloat16 *outH, *outL;
    float *outF, *rowsum;
};

// ---------------- split conversion kernels ----------------
__global__ __launch_bounds__(256) void split_kernel(const float* __restrict__ in,
                                                    __nv_bfloat16* __restrict__ h,
                                                    __nv_bfloat16* __restrict__ l, int n) {
    int i = blockIdx.x * 256 + threadIdx.x;
    if (i < n) {
        float v = in[i];
        __nv_bfloat16 hi = __float2bfloat16(v);
        h[i] = hi;
        l[i] = __float2bfloat16(v - __bfloat162float(hi));
    }
}

struct WS { const float* W[4]; __nv_bfloat16 *th[4], *tl[4]; };
__global__ __launch_bounds__(256) void wsplit4_kernel(WS ws) {
    __shared__ float t[32][33];
    const float* W = ws.W[blockIdx.z];
    __nv_bfloat16* th = ws.th[blockIdx.z];
    __nv_bfloat16* tl = ws.tl[blockIdx.z];
    int n0 = blockIdx.x * 32, k0 = blockIdx.y * 32;
    int tx = threadIdx.x & 31, ty = threadIdx.x >> 5;
#pragma unroll
    for (int r = ty; r < 32; r += 8)
        t[r][tx] = W[(size_t)(k0 + r) * DIM + n0 + tx];
    __syncthreads();
#pragma unroll
    for (int r = ty; r < 32; r += 8) {
        float v = t[tx][r];
        __nv_bfloat16 hi = __float2bfloat16(v);
        size_t idx = (size_t)(n0 + r) * DIM + k0 + tx;
        th[idx] = hi;
        tl[idx] = __float2bfloat16(v - __bfloat162float(hi));
    }
}

// ---------------- mma.sync split-bf16 GEMM: CTA 64x64, 4 warps (2M x 2N, 32x32) ---
// Target 5 CTAs/SM (20 warps). Same per-warp mainloop as the 928us config.
// modes: 0 Q/K head-split hi/lo, 1 V transposed hi/lo, 2 fp32 out (+bias),
//        3 exp(scores) -> P hi/lo + atomic rowsum, 4 merged / rowsum
__global__ __launch_bounds__(128, 5) void gemm_kernel(GP P)
{
    extern __shared__ char smem[];
    constexpr int NT = 4;
    constexpr int ROWB = 80;
    constexpr int A_H = 0;
    constexpr int A_L = 64 * ROWB;            // 5120
    constexpr int B_H = 2 * 64 * ROWB;        // 10240
    constexpr int B_L = 3 * 64 * ROWB;        // 15360
    constexpr int STAGE = 4 * 64 * ROWB;      // 20480

    const int tid = threadIdx.x;
    const int w = tid >> 5, lane = tid & 31;
    const int g = lane >> 2, t = lane & 3;
    const int wm = w & 1, wn = w >> 1;        // 2 x 2 warps, warp tile 32x32
    const int bx = blockIdx.x, by = blockIdx.y, bz = blockIdx.z;
    const __nv_bfloat16* Ah = P.Ah + (size_t)bz * P.bStrideA;
    const __nv_bfloat16* Al = P.Al + (size_t)bz * P.bStrideA;
    const __nv_bfloat16* Bh = P.Bh + (size_t)bz * P.bStrideB;
    const __nv_bfloat16* Bl = P.Bl + (size_t)bz * P.bStrideB;
    const long strideA = P.strideA, strideB = P.strideB;

    const int m0 = by * 64, n0 = bx * 64;
    const int nch = P.Ktot >> 5;
    const uint32_t sb = smem_u32(smem);

    float acc[2][NT][4];
#pragma unroll
    for (int i = 0; i < 2; i++)
#pragma unroll
        for (int j = 0; j < NT; j++)
#pragma unroll
            for (int k = 0; k < 4; k++) acc[i][j][k] = 0.f;

    auto stage_load = [&](int buf, int c) {
        const int k0 = c << 5;
        const uint32_t so = sb + buf * STAGE;
#pragma unroll
        for (int i = tid; i < 256; i += 128) {
            int r = i >> 2, cc = i & 3;
            uint32_t off = r * ROWB + cc * 16;
            cp16(so + A_H + off, Ah + (size_t)(m0 + r) * strideA + k0 + cc * 8);
            cp16(so + A_L + off, Al + (size_t)(m0 + r) * strideA + k0 + cc * 8);
            cp16(so + B_H + off, Bh + (size_t)(n0 + r) * strideB + k0 + cc * 8);
            cp16(so + B_L + off, Bl + (size_t)(n0 + r) * strideB + k0 + cc * 8);
        }
        asm volatile("cp.async.commit_group;");
    };

    stage_load(0, 0);
    for (int c = 0; c < nch; c++) {
        const int buf = c & 1;
        if (c + 1 < nch) {
            stage_load(buf ^ 1, c + 1);
            asm volatile("cp.async.wait_group 1;");
        } else {
            asm volatile("cp.async.wait_group 0;");
        }
        __syncthreads();

        const char* s = smem + buf * STAGE;
#pragma unroll
        for (int ks = 0; ks < 2; ks++) {
            const int kb = ks * 32 + t * 4;
            uint32_t ah[2][4], al[2][4], bh[NT][2], bl[NT][2];
#pragma unroll
            for (int mt = 0; mt < 2; mt++) {
                const char* p = s + (wm * 32 + mt * 16 + g) * ROWB + kb;
                ah[mt][0] = *(const uint32_t*)(p + A_H);
                ah[mt][1] = *(const uint32_t*)(p + A_H + 8 * ROWB);
                ah[mt][2] = *(const uint32_t*)(p + A_H + 16);
                ah[mt][3] = *(const uint32_t*)(p + A_H + 8 * ROWB + 16);
                al[mt][0] = *(const uint32_t*)(p + A_L);
                al[mt][1] = *(const uint32_t*)(p + A_L + 8 * ROWB);
                al[mt][2] = *(const uint32_t*)(p + A_L + 16);
                al[mt][3] = *(const uint32_t*)(p + A_L + 8 * ROWB + 16);
            }
#pragma unroll
            for (int nt = 0; nt < NT; nt++) {
                const char* p = s + (wn * 32 + nt * 8 + g) * ROWB + kb;
                bh[nt][0] = *(const uint32_t*)(p + B_H);
                bh[nt][1] = *(const uint32_t*)(p + B_H + 16);
                bl[nt][0] = *(const uint32_t*)(p + B_L);
                bl[nt][1] = *(const uint32_t*)(p + B_L + 16);
            }
#pragma unroll
            for (int mt = 0; mt < 2; mt++)
#pragma unroll
                for (int nt = 0; nt < NT; nt++) {
                    mma_bf16(acc[mt][nt], ah[mt], bh[nt]);
                    mma_bf16(acc[mt][nt], ah[mt], bl[nt]);
                    mma_bf16(acc[mt][nt], al[mt], bh[nt]);
                }
        }
        __syncthreads();
    }

    // ---------------- epilogue ----------------
    const int mode = P.mode;
    if (mode == 3) {
        float rs[2][2] = {};
#pragma unroll
        for (int mt = 0; mt < 2; mt++)
#pragma unroll
            for (int nt = 0; nt < NT; nt++)
#pragma unroll
                for (int p = 0; p < 2; p++) {
                    float e0 = __expf(acc[mt][nt][2 * p + 0]);
                    float e1 = __expf(acc[mt][nt][2 * p + 1]);
                    acc[mt][nt][2 * p + 0] = e0;
                    acc[mt][nt][2 * p + 1] = e1;
                    rs[mt][p] += e0 + e1;
                }
#pragma unroll
        for (int mt = 0; mt < 2; mt++)
#pragma unroll
            for (int p = 0; p < 2; p++) {
                int row = m0 + wm * 32 + mt * 16 + g + 8 * p;
#pragma unroll
                for (int nt = 0; nt < NT; nt++) {
                    int col = n0 + wn * 32 + nt * 8 + 2 * t;
                    size_t ofs = (size_t)bz * SEQ * SEQ + (size_t)row * SEQ + col;
                    uint32_t hh, ll;
                    split2(acc[mt][nt][2 * p + 0], acc[mt][nt][2 * p + 1], hh, ll);
                    *(uint32_t*)(P.outH + ofs) = hh;
                    *(uint32_t*)(P.outL + ofs) = ll;
                }
                float s2 = rs[mt][p];
                s2 += __shfl_xor_sync(0xffffffffu, s2, 1);
                s2 += __shfl_xor_sync(0xffffffffu, s2, 2);
                if (t == 0) atomicAdd(&P.rowsum[bz * SEQ + row], s2);
            }
        return;
    }

#pragma unroll
    for (int mt = 0; mt < 2; mt++)
#pragma unroll
        for (int nt = 0; nt < NT; nt++)
#pragma unroll
            for (int p = 0; p < 2; p++) {
                int row = m0 + wm * 32 + mt * 16 + g + 8 * p;
                int col = n0 + wn * 32 + nt * 8 + 2 * t;
                float v0 = acc[mt][nt][2 * p + 0];
                float v1 = acc[mt][nt][2 * p + 1];
                if (mode == 0 || mode == 1) {
                    int b = row >> 11, sq = row & (SEQ - 1);
                    v0 = (v0 + P.bias[col]) * P.scale;
                    v1 = (v1 + P.bias[col + 1]) * P.scale;
#pragma unroll
                    for (int e = 0; e < 2; e++) {
                        int cc = col + e;
                        float v = e ? v1 : v0;
                        int h = cc >> 6, hd = cc & (HDIM - 1);
                        __nv_bfloat16 hi = __float2bfloat16(v);
                        __nv_bfloat16 lo = __float2bfloat16(v - __bfloat162float(hi));
                        size_t idx = (mode == 0)
                            ? ((((size_t)b * NH + h) * SEQ + sq) * HDIM + hd)
                            : ((((size_t)b * NH + h) * HDIM + hd) * SEQ + sq);
                        P.outH[idx] = hi;
                        P.outL[idx] = lo;
                    }
                } else if (mode == 2) {
                    *(float2*)(P.outF + (size_t)row * DIM + col)
                        = make_float2(v0 + P.bias[col], v1 + P.bias[col + 1]);
                } else {  // mode 4
                    float inv = 1.0f / P.rowsum[bz * SEQ + row];
                    v0 *= inv;
                    v1 *= inv;
                    int b = bz >> 4, h = bz & (NH - 1);
                    size_t base = ((size_t)b * SEQ + row) * DIM + h * HDIM + col;
                    uint32_t hh, ll;
                    split2(v0, v1, hh, ll);
                    *(uint32_t*)(P.outH + base) = hh;
                    *(uint32_t*)(P.outL + base) = ll;
                }
            }
}

// ---------------- host ----------------
static void* sym(const void* s) { void* p; cudaGetSymbolAddress(&p, s); return p; }

extern "C" void kernel_launch(void* const* d_in, const int* in_sizes, int n_in,
                              void* d_out, int out_size)
{
    const float* x  = (const float*)d_in[0];
    const float* Wq = (const float*)d_in[1];
    const float* bq = (const float*)d_in[2];
    const float* Wk = (const float*)d_in[3];
    const float* bk = (const float*)d_in[4];
    const float* Wv = (const float*)d_in[5];
    const float* bv = (const float*)d_in[6];
    const float* Wo = (const float*)d_in[7];
    const float* bo = (const float*)d_in[8];
    float* out = (float*)d_out;

    constexpr int SMEM = 2 * 4 * 64 * 80;   // 40960
    cudaFuncSetAttribute(gemm_kernel, cudaFuncAttributeMaxDynamicSharedMemorySize, SMEM);

    __nv_bfloat16 *xh = (__nv_bfloat16*)sym(g_xh), *xl = (__nv_bfloat16*)sym(g_xl);
    __nv_bfloat16 *wqh = (__nv_bfloat16*)sym(g_Wqh), *wql = (__nv_bfloat16*)sym(g_Wql);
    __nv_bfloat16 *wkh = (__nv_bfloat16*)sym(g_Wkh), *wkl = (__nv_bfloat16*)sym(g_Wkl);
    __nv_bfloat16 *wvh = (__nv_bfloat16*)sym(g_Wvh), *wvl = (__nv_bfloat16*)sym(g_Wvl);
    __nv_bfloat16 *woh = (__nv_bfloat16*)sym(g_Woh), *wol = (__nv_bfloat16*)sym(g_Wol);
    __nv_bfloat16 *qh = (__nv_bfloat16*)sym(g_Qh), *ql = (__nv_bfloat16*)sym(g_Ql);
    __nv_bfloat16 *kh = (__nv_bfloat16*)sym(g_Kh), *kl = (__nv_bfloat16*)sym(g_Kl);
    __nv_bfloat16 *vth = (__nv_bfloat16*)sym(g_Vth), *vtl = (__nv_bfloat16*)sym(g_Vtl);
    __nv_bfloat16 *pwh = (__nv_bfloat16*)sym(g_Ph), *pwl = (__nv_bfloat16*)sym(g_Pl);
    __nv_bfloat16 *ah = (__nv_bfloat16*)sym(g_Ah), *al = (__nv_bfloat16*)sym(g_Al);
    float* rsum = (float*)sym(g_rowsum);

    cudaMemsetAsync(rsum, 0, BH * SEQ * sizeof(float), 0);

    split_kernel<<<(MROWS * DIM + 255) / 256, 256>>>(x, xh, xl, MROWS * DIM);

    WS ws;
    ws.W[0] = Wq;  ws.th[0] = wqh;  ws.tl[0] = wql;
    ws.W[1] = Wk;  ws.th[1] = wkh;  ws.tl[1] = wkl;
    ws.W[2] = Wv;  ws.th[2] = wvh;  ws.tl[2] = wvl;
    ws.W[3] = Wo;  ws.th[3] = woh;  ws.tl[3] = wol;
    wsplit4_kernel<<<dim3(DIM / 32, DIM / 32, 4), 256>>>(ws);

    dim3 blk(128);
    dim3 gproj(DIM / 64, MROWS / 64, 1);   // 16 x 64 = 1024 blocks

    GP q = {xh, xl, wqh, wql, DIM, 0, DIM, 0, bq, 0.125f, DIM, 0, qh, ql, nullptr, nullptr};
    GP k = {xh, xl, wkh, wkl, DIM, 0, DIM, 0, bk, 1.0f,   DIM, 0, kh, kl, nullptr, nullptr};
    GP v = {xh, xl, wvh, wvl, DIM, 0, DIM, 0, bv, 1.0f,   DIM, 1, vth, vtl, nullptr, nullptr};
    GP s = {qh, ql, kh, kl, HDIM, (long)SEQ * HDIM, HDIM, (long)SEQ * HDIM,
            nullptr, 1.0f, HDIM, 3, pwh, pwl, nullptr, rsum};
    GP av = {pwh, pwl, vth, vtl, SEQ, (long)SEQ * SEQ, SEQ, (long)HDIM * SEQ,
             nullptr, 1.0f, SEQ, 4, ah, al, nullptr, rsum};
    GP o = {ah, al, woh, wol, DIM, 0, DIM, 0, bo, 1.0f, DIM, 2,
            nullptr, nullptr, out, nullptr};

    gemm_kernel<<<gproj, blk, SMEM>>>(q);
    gemm_kernel<<<gproj, blk, SMEM>>>(k);
    gemm_kernel<<<gproj, blk, SMEM>>>(v);
    gemm_kernel<<<dim3(SEQ / 64, SEQ / 64, BH), blk, SMEM>>>(s);
    gemm_kernel<<<dim3(1, SEQ / 64, BH), blk, SMEM>>>(av);
    gemm_kernel<<<gproj, blk, SMEM>>>(o);
}